// round 2
// baseline (speedup 1.0000x reference)
#include <cuda_runtime.h>
#include <math.h>

#define Bc   8
#define Sc   8192
#define Vc   64
#define Dc   256
#define DVc  32
#define DAGG 224     // D - DV
#define NTOK (Bc*Sc) // 65536
#define NBV  (Bc*Vc) // 512

// ---------------- scratch (device globals; no allocation) ----------------
__device__ float g_A[DAGG], g_Bv[DAGG], g_C[DAGG];
__device__ float g_pa[3][Dc], g_pb[3][Dc], g_pc[3][Dc];   // 0=q,1=k,2=v
__device__ float g_Pvar[3][Vc][Dc];                       // var_emb @ W[0:32,:]
__device__ int   g_cnt[NBV];
__device__ float g_sv[NBV], g_st[NBV];
__device__ int   g_off[NBV];
__device__ int   g_cur[NBV];
__device__ int   g_idx[NTOK];
__device__ float g_ctx[Bc][Dc];
__device__ int   g_maskflags;   // bit0: byte layout, bit1: float layout

// ---------------- mask reader (dtype detected at runtime) ----------------
__device__ __forceinline__ bool is_valid(const void* mask, int t) {
    int fl = g_maskflags;
    if (fl & 2) return ((const float*)mask)[t] != 0.0f;
    if (fl & 1) return ((const unsigned char*)mask)[t] != 0;
    return ((const int*)mask)[t] != 0;
}

// ---------------- K0: zero scratch ----------------
__global__ void kzero() {
    int i = blockIdx.x * blockDim.x + threadIdx.x;
    if (i < NBV) { g_cnt[i] = 0; g_sv[i] = 0.f; g_st[i] = 0.f; g_cur[i] = 0; }
    if (i < Bc * Dc) ((float*)g_ctx)[i] = 0.f;
    if (i == 0) g_maskflags = 0;
}

// ---------------- K1: rank-2 embedding collapse (A,B,C) + mask dtype detect ----------------
__global__ void kabc(const float* __restrict__ me_w, const float* __restrict__ me_b,
                     const float* __restrict__ time_w, const float* __restrict__ time_b,
                     const float* __restrict__ agg_w, const float* __restrict__ agg_b,
                     const void* __restrict__ mask) {
    if (blockIdx.x == 0) {
        int j = threadIdx.x;
        if (j < DAGG) {
            float a = 0.f, b = 0.f, c = 0.f;
            for (int i = 0; i < Dc; i++) {
                float w = agg_w[i * DAGG + j];
                a += me_w[i] * w;  c += me_b[i] * w;
            }
            for (int i = 0; i < Dc; i++) {
                float w = agg_w[(Dc + i) * DAGG + j];
                b += time_w[i] * w;  c += time_b[i] * w;
            }
            g_A[j] = a; g_Bv[j] = b; g_C[j] = c + agg_b[j];
        }
    } else {
        // Scan first 65536 bytes (safe under every candidate layout, count=65536 elems)
        const unsigned int* w32 = (const unsigned int*)mask;
        int flags = 0;
        int base = (blockIdx.x - 1) * 2048 + threadIdx.x;
        #pragma unroll
        for (int t = 0; t < 8; t++) {
            unsigned int w = w32[base + t * 256];
            if (w == 0x3f800000u) flags |= 2;     // float32 1.0f pattern
            else if (w > 1u)      flags |= 1;     // packed bytes
        }
        if (__syncthreads_or(flags)) {
            // reduce flags within block
            __shared__ int sfl;
            if (threadIdx.x == 0) sfl = 0;
            __syncthreads();
            if (flags) atomicOr(&sfl, flags);
            __syncthreads();
            if (threadIdx.x == 0 && sfl) atomicOr(&g_maskflags, sfl);
        }
    }
}

// ---------------- K2: projection constants (Pvar, pa, pb, pc) ----------------
__global__ void kproj(const float* __restrict__ var_emb,
                      const float* __restrict__ wq, const float* __restrict__ bq,
                      const float* __restrict__ wk, const float* __restrict__ bk,
                      const float* __restrict__ wv, const float* __restrict__ bvv) {
    int p = blockIdx.y;
    const float* W  = (p == 0) ? wq : (p == 1 ? wk : wv);
    const float* bb = (p == 0) ? bq : (p == 1 ? bk : bvv);
    int row = blockIdx.x;
    int j = threadIdx.x;
    if (row < Vc) {
        const float* ve = &var_emb[row * DVc];
        float s = 0.f;
        #pragma unroll
        for (int i = 0; i < DVc; i++) s += ve[i] * W[i * Dc + j];
        g_Pvar[p][row][j] = s;
    } else {
        const float* src = (row == Vc) ? g_A : (row == Vc + 1 ? g_Bv : g_C);
        float s = 0.f;
        for (int i = 0; i < DAGG; i++) s += src[i] * W[(DVc + i) * Dc + j];
        if      (row == Vc)     g_pa[p][j] = s;
        else if (row == Vc + 1) g_pb[p][j] = s;
        else                    g_pc[p][j] = s + bb[j];
    }
}

// ---------------- K3: per-(b,v) count / sum(values) / sum(times) ----------------
__global__ void kstats(const int* __restrict__ fid, const void* __restrict__ mask,
                       const float* __restrict__ values, const float* __restrict__ times) {
    int t = blockIdx.x * blockDim.x + threadIdx.x;
    if (t >= NTOK) return;
    if (!is_valid(mask, t)) return;
    int b = t >> 13;
    int bv = b * Vc + fid[t];
    atomicAdd(&g_cnt[bv], 1);
    atomicAdd(&g_sv[bv], values[t]);
    atomicAdd(&g_st[bv], times[t]);
}

// ---------------- K4: exclusive prefix sum over 512 counts ----------------
__global__ void koff() {
    __shared__ int sh[NBV];
    int t = threadIdx.x;
    int c = g_cnt[t];
    sh[t] = c;
    __syncthreads();
    for (int o = 1; o < NBV; o <<= 1) {
        int v = (t >= o) ? sh[t - o] : 0;
        __syncthreads();
        sh[t] += v;
        __syncthreads();
    }
    g_off[t] = sh[t] - c;
}

// ---------------- K5: CSR scatter of token indices ----------------
__global__ void kscat(const int* __restrict__ fid, const void* __restrict__ mask) {
    int t = blockIdx.x * blockDim.x + threadIdx.x;
    if (t >= NTOK) return;
    if (!is_valid(mask, t)) return;
    int b = t >> 13;
    int bv = b * Vc + fid[t];
    int pos = atomicAdd(&g_cur[bv], 1);
    g_idx[g_off[bv] + pos] = t & (Sc - 1);
}

// ---------------- K6: segmented attention, 1 block/(b,v), 1 warp/head ----------------
__global__ void __launch_bounds__(256) kattn(const int* __restrict__ fid,
                                             const float* __restrict__ values,
                                             const float* __restrict__ times) {
    int bv = blockIdx.x;
    int b = bv >> 6, v = bv & (Vc - 1);
    int tid = threadIdx.x;            // tid == dimension index (h*32+lane)
    int n = g_cnt[bv];

    float vaL = g_pa[2][tid], vbL = g_pb[2][tid], vcL = g_pc[2][tid];

    if (n == 0) {
        // reference: all-masked segment unmasks s=0 -> attn one-hot -> ctx = v[b,0,:]
        int t0 = b * Sc;
        int f0 = fid[t0];
        float vx = g_Pvar[2][f0][tid] + values[t0] * vaL + times[t0] * vbL + vcL;
        atomicAdd(&g_ctx[b][tid], vx);
        return;
    }

    float cf = (float)n;
    float mv = g_sv[bv] / cf, mt = g_st[bv] / cf;
    float q   = g_Pvar[0][v][tid] + mv * g_pa[0][tid] + mt * g_pb[0][tid] + g_pc[0][tid];
    float Kv  = g_Pvar[1][v][tid];
    float kaL = g_pa[1][tid], kbL = g_pb[1][tid], kcL = g_pc[1][tid];
    float Vv  = g_Pvar[2][v][tid];

    float m = -1e30f, l = 0.f, acc = 0.f;
    int base = g_off[bv];
    const int tb = b * Sc;
    const float scale = 0.17677669529663687f;  // 1/sqrt(32)

    for (int i = 0; i < n; i++) {
        int s = g_idx[base + i];
        float val = values[tb + s], tt = times[tb + s];
        float kx = Kv + val * kaL + tt * kbL + kcL;
        float p = q * kx;
        #pragma unroll
        for (int o = 16; o > 0; o >>= 1) p += __shfl_xor_sync(0xffffffffu, p, o);
        p *= scale;
        float nm = fmaxf(m, p);
        float sc = expf(m - nm);
        float e  = expf(p - nm);
        float vx = Vv + val * vaL + tt * vbL + vcL;
        l   = l * sc + e;
        acc = acc * sc + e * vx;
        m = nm;
    }
    atomicAdd(&g_ctx[b][tid], acc / l);
}

// ---------------- K7: output MLP ----------------
__global__ void kfinal(const float* __restrict__ wo, const float* __restrict__ bo,
                       const float* __restrict__ cw1, const float* __restrict__ cb1,
                       const float* __restrict__ cw2, const float* __restrict__ cb2,
                       float* __restrict__ out) {
    int b = blockIdx.x, j = threadIdx.x;
    __shared__ float sm[Dc], sf[Dc], red[Dc];
    sm[j] = g_ctx[b][j] * (1.0f / Vc);
    __syncthreads();
    float f = bo[j];
    for (int i = 0; i < Dc; i++) f += sm[i] * wo[i * Dc + j];
    sf[j] = f;
    __syncthreads();
    float h = cb1[j];
    for (int i = 0; i < Dc; i++) h += sf[i] * cw1[i * Dc + j];
    h = fmaxf(h, 0.f);
    red[j] = h * cw2[j];
    __syncthreads();
    for (int s = 128; s > 0; s >>= 1) {
        if (j < s) red[j] += red[j + s];
        __syncthreads();
    }
    if (j == 0) out[b] = red[0] + cb2[0];
}

// ---------------- launch ----------------
extern "C" void kernel_launch(void* const* d_in, const int* in_sizes, int n_in,
                              void* d_out, int out_size) {
    const float* times   = (const float*)d_in[0];
    const int*   fid     = (const int*)  d_in[1];
    const float* values  = (const float*)d_in[2];
    const void*  mask    = (const void*) d_in[3];
    const float* me_w    = (const float*)d_in[4];
    const float* me_b    = (const float*)d_in[5];
    const float* var_emb = (const float*)d_in[6];
    const float* time_w  = (const float*)d_in[7];
    const float* time_b  = (const float*)d_in[8];
    const float* agg_w   = (const float*)d_in[9];
    const float* agg_b   = (const float*)d_in[10];
    const float* wq = (const float*)d_in[11]; const float* bq  = (const float*)d_in[12];
    const float* wk = (const float*)d_in[13]; const float* bk  = (const float*)d_in[14];
    const float* wv = (const float*)d_in[15]; const float* bvv = (const float*)d_in[16];
    const float* wo = (const float*)d_in[17]; const float* bo  = (const float*)d_in[18];
    const float* cw1 = (const float*)d_in[19]; const float* cb1 = (const float*)d_in[20];
    const float* cw2 = (const float*)d_in[21]; const float* cb2 = (const float*)d_in[22];
    float* out = (float*)d_out;

    kzero <<<4, 512>>>();
    kabc  <<<9, 256>>>(me_w, me_b, time_w, time_b, agg_w, agg_b, mask);
    kproj <<<dim3(67, 3), 256>>>(var_emb, wq, bq, wk, bk, wv, bvv);
    kstats<<<64, 1024>>>(fid, mask, values, times);
    koff  <<<1, 512>>>();
    kscat <<<64, 1024>>>(fid, mask);
    kattn <<<512, 256>>>(fid, values, times);
    kfinal<<<8, 256>>>(wo, bo, cw1, cb1, cw2, cb2, out);
}

// round 3
// speedup vs baseline: 1.6609x; 1.6609x over previous
#include <cuda_runtime.h>
#include <math.h>

#define Bc   8
#define Sc   8192
#define Vc   64
#define Dc   256
#define DVc  32
#define DAGG 224     // D - DV
#define NTOK (Bc*Sc) // 65536
#define NBV  (Bc*Vc) // 512
#define CAP  Sc      // worst-case tokens per (b,v) segment

// ---------------- scratch (device globals; no allocation) ----------------
__device__ float  g_A[DAGG], g_Bv[DAGG], g_C[DAGG];
__device__ float  g_pa[3][Dc], g_pb[3][Dc], g_pc[3][Dc];   // 0=q,1=k,2=v
__device__ float  g_Pvar[3][Vc][Dc];                       // var_emb @ W[0:32,:]
__device__ int    g_cnt[NBV];
__device__ float  g_sv[NBV], g_st[NBV];
__device__ float2 g_tok[NBV * CAP];                        // (val,tt) per segment
__device__ float  g_ctx[Bc][Dc];
__device__ int    g_maskflags = 0;   // bit0: byte layout, bit1: float layout (never re-zeroed; OR is idempotent)

// ---------------- mask reader (dtype detected at runtime) ----------------
__device__ __forceinline__ bool is_valid(const void* mask, int t, int fl) {
    if (fl & 2) return ((const float*)mask)[t] != 0.0f;
    if (fl & 1) return ((const unsigned char*)mask)[t] != 0;
    return ((const int*)mask)[t] != 0;
}

// ---------------- K1: zero scratch + mask dtype detect + rank-2 collapse ----------------
__global__ void k_init(const float* __restrict__ me_w, const float* __restrict__ me_b,
                       const float* __restrict__ time_w, const float* __restrict__ time_b,
                       const float* __restrict__ agg_w, const float* __restrict__ agg_b,
                       const void* __restrict__ mask) {
    int blk = blockIdx.x;
    if (blk == 0) {
        // A,B,C: collapse the 480x224 agg GEMM applied to rank-2 token embedding
        int j = threadIdx.x;
        if (j < DAGG) {
            float a = 0.f, b = 0.f, c = 0.f;
            for (int i = 0; i < Dc; i++) {
                float w = agg_w[i * DAGG + j];
                a += me_w[i] * w;  c += me_b[i] * w;
            }
            for (int i = 0; i < Dc; i++) {
                float w = agg_w[(Dc + i) * DAGG + j];
                b += time_w[i] * w;  c += time_b[i] * w;
            }
            g_A[j] = a; g_Bv[j] = b; g_C[j] = c + agg_b[j];
        }
    } else if (blk <= 8) {
        // detect mask dtype: scan first 16384 words (= whole mask if byte layout)
        const unsigned int* w32 = (const unsigned int*)mask;
        int flags = 0;
        int base = (blk - 1) * 2048 + threadIdx.x;
        #pragma unroll
        for (int t = 0; t < 8; t++) {
            unsigned int w = w32[base + t * 256];
            if (w == 0x3f800000u) flags |= 2;     // float32 1.0f pattern
            else if (w > 1u)      flags |= 1;     // packed bytes
        }
        __shared__ int sfl;
        if (threadIdx.x == 0) sfl = 0;
        __syncthreads();
        if (flags) atomicOr(&sfl, flags);
        __syncthreads();
        if (threadIdx.x == 0 && sfl) atomicOr(&g_maskflags, sfl);
    } else {
        // zero accumulators
        int i = (blk - 9) * 256 + threadIdx.x;
        if (i < NBV) { g_cnt[i] = 0; g_sv[i] = 0.f; g_st[i] = 0.f; }
        if (i < Bc * Dc) ((float*)g_ctx)[i] = 0.f;
    }
}

// ---------------- K2: projection constants || segment stats + token buckets ----------------
__global__ void k_mid(const float* __restrict__ var_emb,
                      const float* __restrict__ wq, const float* __restrict__ bq,
                      const float* __restrict__ wk, const float* __restrict__ bk,
                      const float* __restrict__ wv, const float* __restrict__ bvv,
                      const int* __restrict__ fid, const void* __restrict__ mask,
                      const float* __restrict__ values, const float* __restrict__ times) {
    int blk = blockIdx.x;
    if (blk < 201) {
        // projection constants: 67 rows x 3 matrices
        int p = blk / 67, row = blk % 67;
        const float* W  = (p == 0) ? wq : (p == 1 ? wk : wv);
        const float* bb = (p == 0) ? bq : (p == 1 ? bk : bvv);
        int j = threadIdx.x;
        if (row < Vc) {
            const float* ve = &var_emb[row * DVc];
            float s = 0.f;
            #pragma unroll
            for (int i = 0; i < DVc; i++) s += ve[i] * W[i * Dc + j];
            g_Pvar[p][row][j] = s;
        } else {
            const float* src = (row == Vc) ? g_A : (row == Vc + 1 ? g_Bv : g_C);
            float s = 0.f;
            for (int i = 0; i < DAGG; i++) s += src[i] * W[(DVc + i) * Dc + j];
            if      (row == Vc)     g_pa[p][j] = s;
            else if (row == Vc + 1) g_pb[p][j] = s;
            else                    g_pc[p][j] = s + bb[j];
        }
    } else {
        // stats + bucket fill: one thread per token
        int t = (blk - 201) * 256 + threadIdx.x;
        int fl = g_maskflags;
        if (!is_valid(mask, t, fl)) return;
        int b = t >> 13;
        int bv = b * Vc + fid[t];
        float val = values[t], tt = times[t];
        int pos = atomicAdd(&g_cnt[bv], 1);
        atomicAdd(&g_sv[bv], val);
        atomicAdd(&g_st[bv], tt);
        g_tok[bv * CAP + pos] = make_float2(val, tt);
    }
}

// ---------------- K3: segmented attention, affine-score form ----------------
// score_h(s) = alpha_h + beta_h*val_s + gamma_h*tt_s   (k projection is affine in (val,tt))
// ctx_d = Vv_d + vc_d + (Sum w*val)*va_d + (Sum w*tt)*vb_d
__global__ void __launch_bounds__(256) k_attn(const int* __restrict__ fid,
                                              const float* __restrict__ values,
                                              const float* __restrict__ times) {
    int bv = blockIdx.x;
    int b = bv >> 6, v = bv & (Vc - 1);
    int tid = threadIdx.x;             // tid == dim index d = h*32+lane
    int lane = tid & 31;
    int n = g_cnt[bv];

    float va = g_pa[2][tid], vb = g_pb[2][tid], vc = g_pc[2][tid];

    if (n == 0) {
        // all-masked segment: reference unmasks s=0 -> ctx = v[b,0,:]
        int t0 = b * Sc;
        float vx = g_Pvar[2][fid[t0]][tid] + values[t0] * va + times[t0] * vb + vc;
        atomicAdd(&g_ctx[b][tid], vx);
        return;
    }

    float inv_n = 1.0f / (float)n;
    float mv = g_sv[bv] * inv_n, mt = g_st[bv] * inv_n;
    float q  = g_Pvar[0][v][tid] + mv * g_pa[0][tid] + mt * g_pb[0][tid] + g_pc[0][tid];
    float kk = g_Pvar[1][v][tid] + g_pc[1][tid];

    const float scale = 0.17677669529663687f;  // 1/sqrt(32)
    float al = q * kk, be = q * g_pa[1][tid], ga = q * g_pb[1][tid];
    #pragma unroll
    for (int o = 16; o > 0; o >>= 1) {
        al += __shfl_xor_sync(0xffffffffu, al, o);
        be += __shfl_xor_sync(0xffffffffu, be, o);
        ga += __shfl_xor_sync(0xffffffffu, ga, o);
    }
    al *= scale; be *= scale; ga *= scale;

    // lane-parallel online softmax over this segment's tokens
    float m = -1e30f, l = 0.f, sv = 0.f, st = 0.f;
    const float2* tok = &g_tok[bv * CAP];
    for (int i = lane; i < n; i += 32) {
        float2 vt = tok[i];
        float s  = al + be * vt.x + ga * vt.y;
        float nm = fmaxf(m, s);
        float c  = __expf(m - nm);
        float e  = __expf(s - nm);
        l  = l * c + e;
        sv = sv * c + e * vt.x;
        st = st * c + e * vt.y;
        m = nm;
    }
    // cross-lane merge of (m, l, sv, st)
    #pragma unroll
    for (int o = 16; o > 0; o >>= 1) {
        float m2  = __shfl_xor_sync(0xffffffffu, m, o);
        float l2  = __shfl_xor_sync(0xffffffffu, l, o);
        float sv2 = __shfl_xor_sync(0xffffffffu, sv, o);
        float st2 = __shfl_xor_sync(0xffffffffu, st, o);
        float nm = fmaxf(m, m2);
        float c1 = __expf(m - nm), c2 = __expf(m2 - nm);
        l  = l * c1 + l2 * c2;
        sv = sv * c1 + sv2 * c2;
        st = st * c1 + st2 * c2;
        m = nm;
    }
    float wv = sv / l, wt = st / l;
    float ctx = g_Pvar[2][v][tid] + vc + wv * va + wt * vb;
    atomicAdd(&g_ctx[b][tid], ctx);
}

// ---------------- K4: output MLP ----------------
__global__ void k_final(const float* __restrict__ wo, const float* __restrict__ bo,
                        const float* __restrict__ cw1, const float* __restrict__ cb1,
                        const float* __restrict__ cw2, const float* __restrict__ cb2,
                        float* __restrict__ out) {
    int b = blockIdx.x, j = threadIdx.x;
    __shared__ float sm[Dc], sf[Dc], red[Dc];
    sm[j] = g_ctx[b][j] * (1.0f / Vc);
    __syncthreads();
    float f = bo[j];
    for (int i = 0; i < Dc; i++) f += sm[i] * wo[i * Dc + j];
    sf[j] = f;
    __syncthreads();
    float h = cb1[j];
    for (int i = 0; i < Dc; i++) h += sf[i] * cw1[i * Dc + j];
    h = fmaxf(h, 0.f);
    red[j] = h * cw2[j];
    __syncthreads();
    for (int s = 128; s > 0; s >>= 1) {
        if (j < s) red[j] += red[j + s];
        __syncthreads();
    }
    if (j == 0) out[b] = red[0] + cb2[0];
}

// ---------------- launch ----------------
extern "C" void kernel_launch(void* const* d_in, const int* in_sizes, int n_in,
                              void* d_out, int out_size) {
    const float* times   = (const float*)d_in[0];
    const int*   fid     = (const int*)  d_in[1];
    const float* values  = (const float*)d_in[2];
    const void*  mask    = (const void*) d_in[3];
    const float* me_w    = (const float*)d_in[4];
    const float* me_b    = (const float*)d_in[5];
    const float* var_emb = (const float*)d_in[6];
    const float* time_w  = (const float*)d_in[7];
    const float* time_b  = (const float*)d_in[8];
    const float* agg_w   = (const float*)d_in[9];
    const float* agg_b   = (const float*)d_in[10];
    const float* wq = (const float*)d_in[11]; const float* bq  = (const float*)d_in[12];
    const float* wk = (const float*)d_in[13]; const float* bk  = (const float*)d_in[14];
    const float* wv = (const float*)d_in[15]; const float* bvv = (const float*)d_in[16];
    const float* wo = (const float*)d_in[17]; const float* bo  = (const float*)d_in[18];
    const float* cw1 = (const float*)d_in[19]; const float* cb1 = (const float*)d_in[20];
    const float* cw2 = (const float*)d_in[21]; const float* cb2 = (const float*)d_in[22];
    float* out = (float*)d_out;

    k_init <<<25, 256>>>(me_w, me_b, time_w, time_b, agg_w, agg_b, mask);
    k_mid  <<<201 + NTOK / 256, 256>>>(var_emb, wq, bq, wk, bk, wv, bvv,
                                       fid, mask, values, times);
    k_attn <<<NBV, 256>>>(fid, values, times);
    k_final<<<8, 256>>>(wo, bo, cw1, cb1, cw2, cb2, out);
}

// round 4
// speedup vs baseline: 1.8001x; 1.0839x over previous
#include <cuda_runtime.h>
#include <math.h>

#define Bc   8
#define Sc   8192
#define Vc   64
#define Dc   256
#define DVc  32
#define DAGG 224     // D - DV
#define NTOK (Bc*Sc) // 65536
#define NBV  (Bc*Vc) // 512
#define CAP  Sc      // worst-case tokens per (b,v) segment

// ---------------- scratch (device globals; no allocation) ----------------
__device__ float  g_A[DAGG], g_Bv[DAGG], g_C[DAGG];
__device__ float  g_pa[3][Dc], g_pb[3][Dc], g_pc[3][Dc];   // 0=q,1=k,2=v
__device__ float  g_Pvar[3][Vc][Dc];                       // var_emb @ W[0:32,:]
__device__ int    g_cnt[NBV];
__device__ float2 g_tok[NBV * CAP];                        // (val,tt) per segment
__device__ float  g_ctx[Bc][Dc];
__device__ int    g_maskflags = 0;   // bit0: byte layout, bit1: float layout (OR is idempotent across replays)

// ---------------- mask reader (dtype detected at runtime) ----------------
__device__ __forceinline__ bool is_valid(const void* mask, int t, int fl) {
    if (fl & 2) return ((const float*)mask)[t] != 0.0f;
    if (fl & 1) return ((const unsigned char*)mask)[t] != 0;
    return ((const int*)mask)[t] != 0;
}

// ---------------- K1: zero scratch + mask dtype detect + rank-2 collapse ----------------
__global__ void k_init(const float* __restrict__ me_w, const float* __restrict__ me_b,
                       const float* __restrict__ time_w, const float* __restrict__ time_b,
                       const float* __restrict__ agg_w, const float* __restrict__ agg_b,
                       const void* __restrict__ mask) {
    int blk = blockIdx.x;
    if (blk == 0) {
        // A,B,C: collapse the 480x224 agg GEMM applied to rank-2 token embedding
        int j = threadIdx.x;
        if (j < DAGG) {
            float a = 0.f, b = 0.f, c = 0.f;
            for (int i = 0; i < Dc; i++) {
                float w = agg_w[i * DAGG + j];
                a += me_w[i] * w;  c += me_b[i] * w;
            }
            for (int i = 0; i < Dc; i++) {
                float w = agg_w[(Dc + i) * DAGG + j];
                b += time_w[i] * w;  c += time_b[i] * w;
            }
            g_A[j] = a; g_Bv[j] = b; g_C[j] = c + agg_b[j];
        }
    } else if (blk <= 8) {
        // detect mask dtype: scan first 16384 words (= whole mask if byte layout)
        const unsigned int* w32 = (const unsigned int*)mask;
        int flags = 0;
        int base = (blk - 1) * 2048 + threadIdx.x;
        #pragma unroll
        for (int t = 0; t < 8; t++) {
            unsigned int w = w32[base + t * 256];
            if (w == 0x3f800000u) flags |= 2;     // float32 1.0f pattern
            else if (w > 1u)      flags |= 1;     // packed bytes
        }
        __shared__ int sfl;
        if (threadIdx.x == 0) sfl = 0;
        __syncthreads();
        if (flags) atomicOr(&sfl, flags);
        __syncthreads();
        if (threadIdx.x == 0 && sfl) atomicOr(&g_maskflags, sfl);
    } else {
        // zero accumulators
        int i = (blk - 9) * 256 + threadIdx.x;
        if (i < NBV) g_cnt[i] = 0;
        if (i < Bc * Dc) ((float*)g_ctx)[i] = 0.f;
    }
}

// ---------------- K2: projection constants || token bucket scatter ----------------
__global__ void k_mid(const float* __restrict__ var_emb,
                      const float* __restrict__ wq, const float* __restrict__ bq,
                      const float* __restrict__ wk, const float* __restrict__ bk,
                      const float* __restrict__ wv, const float* __restrict__ bvv,
                      const int* __restrict__ fid, const void* __restrict__ mask,
                      const float* __restrict__ values, const float* __restrict__ times) {
    int blk = blockIdx.x;
    if (blk < 201) {
        // projection constants: 67 rows x 3 matrices
        int p = blk / 67, row = blk % 67;
        const float* W  = (p == 0) ? wq : (p == 1 ? wk : wv);
        const float* bb = (p == 0) ? bq : (p == 1 ? bk : bvv);
        int j = threadIdx.x;
        if (row < Vc) {
            const float* ve = &var_emb[row * DVc];
            float s = 0.f;
            #pragma unroll
            for (int i = 0; i < DVc; i++) s += ve[i] * W[i * Dc + j];
            g_Pvar[p][row][j] = s;
        } else {
            const float* src = (row == Vc) ? g_A : (row == Vc + 1 ? g_Bv : g_C);
            float s = 0.f;
            for (int i = 0; i < DAGG; i++) s += src[i] * W[(DVc + i) * Dc + j];
            if      (row == Vc)     g_pa[p][j] = s;
            else if (row == Vc + 1) g_pb[p][j] = s;
            else                    g_pc[p][j] = s + bb[j];
        }
    } else {
        // bucket fill: one thread per token; only ONE atomic per valid token
        int t = (blk - 201) * 256 + threadIdx.x;
        int fl = g_maskflags;
        if (!is_valid(mask, t, fl)) return;
        int b = t >> 13;
        int bv = b * Vc + fid[t];
        int pos = atomicAdd(&g_cnt[bv], 1);
        g_tok[bv * CAP + pos] = make_float2(values[t], times[t]);
    }
}

// ---------------- K3: segmented attention, affine-score form ----------------
// score_h(s) = alpha_h + beta_h*val_s + gamma_h*tt_s   (k projection is affine in (val,tt))
// ctx_d = Vv_d + vc_d + (Sum w*val/Sum w)*va_d + (Sum w*tt/Sum w)*vb_d
__global__ void __launch_bounds__(256) k_attn(const int* __restrict__ fid,
                                              const float* __restrict__ values,
                                              const float* __restrict__ times) {
    int bv = blockIdx.x;
    int b = bv >> 6, v = bv & (Vc - 1);
    int tid = threadIdx.x;             // tid == dim index d = h*32+lane
    int lane = tid & 31;
    int n = g_cnt[bv];

    float va = g_pa[2][tid], vb = g_pb[2][tid], vc = g_pc[2][tid];

    if (n == 0) {
        // all-masked segment: reference unmasks s=0 -> ctx = v[b,0,:]
        int t0 = b * Sc;
        float vx = g_Pvar[2][fid[t0]][tid] + values[t0] * va + times[t0] * vb + vc;
        atomicAdd(&g_ctx[b][tid], vx);
        return;
    }

    const float2* tok = &g_tok[bv * CAP];

    // pass 1: segment means (replaces global float atomics in k_mid)
    float s_v = 0.f, s_t = 0.f;
    for (int i = lane; i < n; i += 32) {
        float2 vt = tok[i];
        s_v += vt.x; s_t += vt.y;
    }
    #pragma unroll
    for (int o = 16; o > 0; o >>= 1) {
        s_v += __shfl_xor_sync(0xffffffffu, s_v, o);
        s_t += __shfl_xor_sync(0xffffffffu, s_t, o);
    }
    float inv_n = 1.0f / (float)n;
    float mv = s_v * inv_n, mt = s_t * inv_n;

    float q  = g_Pvar[0][v][tid] + mv * g_pa[0][tid] + mt * g_pb[0][tid] + g_pc[0][tid];
    float kk = g_Pvar[1][v][tid] + g_pc[1][tid];

    const float scale = 0.17677669529663687f;  // 1/sqrt(32)
    float al = q * kk, be = q * g_pa[1][tid], ga = q * g_pb[1][tid];
    #pragma unroll
    for (int o = 16; o > 0; o >>= 1) {
        al += __shfl_xor_sync(0xffffffffu, al, o);
        be += __shfl_xor_sync(0xffffffffu, be, o);
        ga += __shfl_xor_sync(0xffffffffu, ga, o);
    }
    al *= scale; be *= scale; ga *= scale;

    // pass 2: lane-parallel online softmax over this segment's tokens
    float m = -1e30f, l = 0.f, sv = 0.f, st = 0.f;
    for (int i = lane; i < n; i += 32) {
        float2 vt = tok[i];
        float s  = al + be * vt.x + ga * vt.y;
        float nm = fmaxf(m, s);
        float c  = __expf(m - nm);
        float e  = __expf(s - nm);
        l  = l * c + e;
        sv = sv * c + e * vt.x;
        st = st * c + e * vt.y;
        m = nm;
    }
    // cross-lane merge of (m, l, sv, st)
    #pragma unroll
    for (int o = 16; o > 0; o >>= 1) {
        float m2  = __shfl_xor_sync(0xffffffffu, m, o);
        float l2  = __shfl_xor_sync(0xffffffffu, l, o);
        float sv2 = __shfl_xor_sync(0xffffffffu, sv, o);
        float st2 = __shfl_xor_sync(0xffffffffu, st, o);
        float nm = fmaxf(m, m2);
        float c1 = __expf(m - nm), c2 = __expf(m2 - nm);
        l  = l * c1 + l2 * c2;
        sv = sv * c1 + sv2 * c2;
        st = st * c1 + st2 * c2;
        m = nm;
    }
    float wv = sv / l, wt = st / l;
    float ctx = g_Pvar[2][v][tid] + vc + wv * va + wt * vb;
    atomicAdd(&g_ctx[b][tid], ctx);
}

// ---------------- K4: output MLP, 1024 threads/block, 4-way i-split ----------------
__global__ void __launch_bounds__(1024) k_final(
        const float* __restrict__ wo, const float* __restrict__ bo,
        const float* __restrict__ cw1, const float* __restrict__ cb1,
        const float* __restrict__ cw2, const float* __restrict__ cb2,
        float* __restrict__ out) {
    int b = blockIdx.x;
    int tid = threadIdx.x;
    int r = tid >> 8, j = tid & 255;   // r: i-partition (0..3), j: output column
    __shared__ float sm[Dc];
    __shared__ float part[4][Dc];
    __shared__ float sf[Dc];

    if (tid < Dc) sm[tid] = g_ctx[b][tid] * (1.0f / Vc);
    __syncthreads();

    // GEMV1: f = sm @ wo + bo   (each thread: 64 independent coalesced loads)
    float acc = 0.f;
    #pragma unroll 16
    for (int ii = 0; ii < 64; ii++) {
        int i = ii * 4 + r;
        acc += sm[i] * wo[i * Dc + j];
    }
    part[r][j] = acc;
    __syncthreads();
    if (r == 0) sf[j] = part[0][j] + part[1][j] + part[2][j] + part[3][j] + bo[j];
    __syncthreads();

    // GEMV2: h = relu(sf @ cw1 + cb1); out = h . cw2 + cb2
    acc = 0.f;
    #pragma unroll 16
    for (int ii = 0; ii < 64; ii++) {
        int i = ii * 4 + r;
        acc += sf[i] * cw1[i * Dc + j];
    }
    part[r][j] = acc;
    __syncthreads();
    if (r == 0) {
        float h = part[0][j] + part[1][j] + part[2][j] + part[3][j] + cb1[j];
        h = fmaxf(h, 0.f);
        sm[j] = h * cw2[j];    // reuse sm as reduction buffer
    }
    __syncthreads();
    #pragma unroll
    for (int s = 128; s > 0; s >>= 1) {
        if (tid < s) sm[tid] += sm[tid + s];
        __syncthreads();
    }
    if (tid == 0) out[b] = sm[0] + cb2[0];
}

// ---------------- launch ----------------
extern "C" void kernel_launch(void* const* d_in, const int* in_sizes, int n_in,
                              void* d_out, int out_size) {
    const float* times   = (const float*)d_in[0];
    const int*   fid     = (const int*)  d_in[1];
    const float* values  = (const float*)d_in[2];
    const void*  mask    = (const void*) d_in[3];
    const float* me_w    = (const float*)d_in[4];
    const float* me_b    = (const float*)d_in[5];
    const float* var_emb = (const float*)d_in[6];
    const float* time_w  = (const float*)d_in[7];
    const float* time_b  = (const float*)d_in[8];
    const float* agg_w   = (const float*)d_in[9];
    const float* agg_b   = (const float*)d_in[10];
    const float* wq = (const float*)d_in[11]; const float* bq  = (const float*)d_in[12];
    const float* wk = (const float*)d_in[13]; const float* bk  = (const float*)d_in[14];
    const float* wv = (const float*)d_in[15]; const float* bvv = (const float*)d_in[16];
    const float* wo = (const float*)d_in[17]; const float* bo  = (const float*)d_in[18];
    const float* cw1 = (const float*)d_in[19]; const float* cb1 = (const float*)d_in[20];
    const float* cw2 = (const float*)d_in[21]; const float* cb2 = (const float*)d_in[22];
    float* out = (float*)d_out;

    k_init <<<25, 256>>>(me_w, me_b, time_w, time_b, agg_w, agg_b, mask);
    k_mid  <<<201 + NTOK / 256, 256>>>(var_emb, wq, bq, wk, bk, wv, bvv,
                                       fid, mask, values, times);
    k_attn <<<NBV, 256>>>(fid, values, times);
    k_final<<<8, 1024>>>(wo, bo, cw1, cb1, cw2, cb2, out);
}

// round 5
// speedup vs baseline: 2.8277x; 1.5708x over previous
#include <cuda_runtime.h>
#include <math.h>

#define Bc   8
#define Sc   8192
#define Vc   64
#define Dc   256
#define DVc  32
#define DAGG 224     // D - DV
#define NTOK (Bc*Sc) // 65536
#define NBV  (Bc*Vc) // 512
#define CAP  Sc      // worst-case tokens per (b,v) segment
#define ABC_BLKS 32

// ---------------- scratch (device globals; no allocation) ----------------
__device__ float  g_A[DAGG], g_Bv[DAGG], g_C[DAGG];
__device__ float  g_part[ABC_BLKS][3][DAGG];
__device__ int    g_abc_ctr = 0;                           // self-resetting
__device__ float  g_pa[3][Dc], g_pb[3][Dc], g_pc[3][Dc];   // 0=q,1=k,2=v
__device__ float  g_Pvar[3][Vc][Dc];                       // var_emb @ W[0:32,:]
__device__ int    g_cnt[NBV];
__device__ float2 g_tok[NBV * CAP];                        // (val,tt) per segment
__device__ float  g_ctx[Bc][Dc];
__device__ int    g_maskflags = 0;   // bit0: byte layout, bit1: float layout (OR idempotent across replays)

// ---------------- mask reader (dtype detected at runtime) ----------------
__device__ __forceinline__ bool is_valid(const void* mask, int t, int fl) {
    if (fl & 2) return ((const float*)mask)[t] != 0.0f;
    if (fl & 1) return ((const unsigned char*)mask)[t] != 0;
    return ((const int*)mask)[t] != 0;
}

// ---------------- K1: parallel ABC collapse + mask detect + zero ----------------
__global__ void k_init(const float* __restrict__ me_w, const float* __restrict__ me_b,
                       const float* __restrict__ time_w, const float* __restrict__ time_b,
                       const float* __restrict__ agg_w, const float* __restrict__ agg_b,
                       const void* __restrict__ mask) {
    int blk = blockIdx.x;
    if (blk < ABC_BLKS) {
        // partial A,B,C over 16 of 512 virtual input rows
        int j = threadIdx.x;
        __shared__ bool isLast;
        if (j < DAGG) {
            float a = 0.f, b = 0.f, c = 0.f;
            int i0 = blk * 16;
            #pragma unroll
            for (int ii = 0; ii < 16; ii++) {
                int i = i0 + ii;
                if (i < 256) {
                    float w = agg_w[i * DAGG + j];
                    a += me_w[i] * w;  c += me_b[i] * w;
                } else {
                    int k = i - 256;
                    float w = agg_w[(256 + k) * DAGG + j];
                    b += time_w[k] * w;  c += time_b[k] * w;
                }
            }
            g_part[blk][0][j] = a;
            g_part[blk][1][j] = b;
            g_part[blk][2][j] = c;
        }
        __threadfence();
        __syncthreads();
        if (threadIdx.x == 0)
            isLast = (atomicAdd(&g_abc_ctr, 1) == ABC_BLKS - 1);
        __syncthreads();
        if (isLast) {
            if (j < DAGG) {
                float a = 0.f, b = 0.f, c = 0.f;
                #pragma unroll
                for (int r = 0; r < ABC_BLKS; r++) {
                    a += g_part[r][0][j];
                    b += g_part[r][1][j];
                    c += g_part[r][2][j];
                }
                g_A[j] = a; g_Bv[j] = b; g_C[j] = c + agg_b[j];
            }
            if (threadIdx.x == 0) g_abc_ctr = 0;   // reset for next replay
        }
    } else if (blk < ABC_BLKS + 8) {
        // detect mask dtype: scan first 16384 words (= whole mask if byte layout)
        const unsigned int* w32 = (const unsigned int*)mask;
        int flags = 0;
        int base = (blk - ABC_BLKS) * 2048 + threadIdx.x;
        #pragma unroll
        for (int t = 0; t < 8; t++) {
            unsigned int w = w32[base + t * 256];
            if (w == 0x3f800000u) flags |= 2;     // float32 1.0f pattern
            else if (w > 1u)      flags |= 1;     // packed bytes
        }
        __shared__ int sfl;
        if (threadIdx.x == 0) sfl = 0;
        __syncthreads();
        if (flags) atomicOr(&sfl, flags);
        __syncthreads();
        if (threadIdx.x == 0 && sfl) atomicOr(&g_maskflags, sfl);
    } else {
        // zero accumulators
        int i = (blk - ABC_BLKS - 8) * 256 + threadIdx.x;   // 0..2047
        if (i < NBV) g_cnt[i] = 0;
        ((float*)g_ctx)[i] = 0.f;
    }
}

// ---------------- K2: projection constants || token bucket scatter ----------------
__global__ void k_mid(const float* __restrict__ var_emb,
                      const float* __restrict__ wq, const float* __restrict__ bq,
                      const float* __restrict__ wk, const float* __restrict__ bk,
                      const float* __restrict__ wv, const float* __restrict__ bvv,
                      const int* __restrict__ fid, const void* __restrict__ mask,
                      const float* __restrict__ values, const float* __restrict__ times) {
    int blk = blockIdx.x;
    if (blk < 201) {
        // projection constants: 67 rows x 3 matrices
        int p = blk / 67, row = blk % 67;
        const float* W  = (p == 0) ? wq : (p == 1 ? wk : wv);
        const float* bb = (p == 0) ? bq : (p == 1 ? bk : bvv);
        int j = threadIdx.x;
        if (row < Vc) {
            const float* ve = &var_emb[row * DVc];
            float s = 0.f;
            #pragma unroll
            for (int i = 0; i < DVc; i++) s += ve[i] * W[i * Dc + j];
            g_Pvar[p][row][j] = s;
        } else {
            const float* src = (row == Vc) ? g_A : (row == Vc + 1 ? g_Bv : g_C);
            float s = 0.f;
            #pragma unroll 8
            for (int i = 0; i < DAGG; i++) s += src[i] * W[(DVc + i) * Dc + j];
            if      (row == Vc)     g_pa[p][j] = s;
            else if (row == Vc + 1) g_pb[p][j] = s;
            else                    g_pc[p][j] = s + bb[j];
        }
    } else {
        // bucket fill: one thread per token; only ONE atomic per valid token
        int t = (blk - 201) * 256 + threadIdx.x;
        int fl = g_maskflags;
        if (!is_valid(mask, t, fl)) return;
        int b = t >> 13;
        int bv = b * Vc + fid[t];
        int pos = atomicAdd(&g_cnt[bv], 1);
        g_tok[bv * CAP + pos] = make_float2(values[t], times[t]);
    }
}

// ---------------- K3: segmented attention, affine-score form ----------------
__global__ void __launch_bounds__(256) k_attn(const int* __restrict__ fid,
                                              const float* __restrict__ values,
                                              const float* __restrict__ times) {
    int bv = blockIdx.x;
    int b = bv >> 6, v = bv & (Vc - 1);
    int tid = threadIdx.x;             // tid == dim index d = h*32+lane
    int lane = tid & 31;
    int n = g_cnt[bv];

    float va = g_pa[2][tid], vb = g_pb[2][tid], vc = g_pc[2][tid];

    if (n == 0) {
        // all-masked segment: reference unmasks s=0 -> ctx = v[b,0,:]
        int t0 = b * Sc;
        float vx = g_Pvar[2][fid[t0]][tid] + values[t0] * va + times[t0] * vb + vc;
        atomicAdd(&g_ctx[b][tid], vx);
        return;
    }

    const float2* tok = &g_tok[bv * CAP];

    // pass 1: segment means
    float s_v = 0.f, s_t = 0.f;
    for (int i = lane; i < n; i += 32) {
        float2 vt = tok[i];
        s_v += vt.x; s_t += vt.y;
    }
    #pragma unroll
    for (int o = 16; o > 0; o >>= 1) {
        s_v += __shfl_xor_sync(0xffffffffu, s_v, o);
        s_t += __shfl_xor_sync(0xffffffffu, s_t, o);
    }
    float inv_n = 1.0f / (float)n;
    float mv = s_v * inv_n, mt = s_t * inv_n;

    float q  = g_Pvar[0][v][tid] + mv * g_pa[0][tid] + mt * g_pb[0][tid] + g_pc[0][tid];
    float kk = g_Pvar[1][v][tid] + g_pc[1][tid];

    const float scale = 0.17677669529663687f;  // 1/sqrt(32)
    float al = q * kk, be = q * g_pa[1][tid], ga = q * g_pb[1][tid];
    #pragma unroll
    for (int o = 16; o > 0; o >>= 1) {
        al += __shfl_xor_sync(0xffffffffu, al, o);
        be += __shfl_xor_sync(0xffffffffu, be, o);
        ga += __shfl_xor_sync(0xffffffffu, ga, o);
    }
    al *= scale; be *= scale; ga *= scale;

    // pass 2: lane-parallel online softmax
    float m = -1e30f, l = 0.f, sv = 0.f, st = 0.f;
    for (int i = lane; i < n; i += 32) {
        float2 vt = tok[i];
        float s  = al + be * vt.x + ga * vt.y;
        float nm = fmaxf(m, s);
        float c  = __expf(m - nm);
        float e  = __expf(s - nm);
        l  = l * c + e;
        sv = sv * c + e * vt.x;
        st = st * c + e * vt.y;
        m = nm;
    }
    #pragma unroll
    for (int o = 16; o > 0; o >>= 1) {
        float m2  = __shfl_xor_sync(0xffffffffu, m, o);
        float l2  = __shfl_xor_sync(0xffffffffu, l, o);
        float sv2 = __shfl_xor_sync(0xffffffffu, sv, o);
        float st2 = __shfl_xor_sync(0xffffffffu, st, o);
        float nm = fmaxf(m, m2);
        float c1 = __expf(m - nm), c2 = __expf(m2 - nm);
        l  = l * c1 + l2 * c2;
        sv = sv * c1 + sv2 * c2;
        st = st * c1 + st2 * c2;
        m = nm;
    }
    float wv = sv / l, wt = st / l;
    float ctx = g_Pvar[2][v][tid] + vc + wv * va + wt * vb;
    atomicAdd(&g_ctx[b][tid], ctx);
}

// ---------------- K4: output MLP, float4 weights, 16-way i-split ----------------
__global__ void __launch_bounds__(1024) k_final(
        const float* __restrict__ wo, const float* __restrict__ bo,
        const float* __restrict__ cw1, const float* __restrict__ cb1,
        const float* __restrict__ cw2, const float* __restrict__ cb2,
        float* __restrict__ out) {
    int b = blockIdx.x;
    int tid = threadIdx.x;
    int r = tid >> 6;        // i-partition 0..15 (16 i's each)
    int c = tid & 63;        // float4 column 0..63
    __shared__ float  sm[Dc];
    __shared__ float4 part[16][64];
    __shared__ float  sf[Dc];
    __shared__ float  red[64];

    if (tid < Dc) sm[tid] = g_ctx[b][tid] * (1.0f / Vc);
    __syncthreads();

    // GEMV1: f = sm @ wo + bo   (16 independent float4 loads per thread)
    {
        const float4* W4 = (const float4*)wo;
        float4 acc = make_float4(0.f, 0.f, 0.f, 0.f);
        #pragma unroll
        for (int ii = 0; ii < 16; ii++) {
            float  s = sm[r * 16 + ii];
            float4 w = W4[(r * 16 + ii) * 64 + c];
            acc.x += s * w.x; acc.y += s * w.y; acc.z += s * w.z; acc.w += s * w.w;
        }
        part[r][c] = acc;
    }
    __syncthreads();
    #pragma unroll
    for (int s = 8; s > 0; s >>= 1) {
        if (r < s) {
            float4 o2 = part[r + s][c];
            part[r][c].x += o2.x; part[r][c].y += o2.y;
            part[r][c].z += o2.z; part[r][c].w += o2.w;
        }
        __syncthreads();
    }
    if (r == 0) {
        float4 bb = ((const float4*)bo)[c];
        float4 t = part[0][c];
        sf[c * 4 + 0] = t.x + bb.x;
        sf[c * 4 + 1] = t.y + bb.y;
        sf[c * 4 + 2] = t.z + bb.z;
        sf[c * 4 + 3] = t.w + bb.w;
    }
    __syncthreads();

    // GEMV2: h = relu(sf @ cw1 + cb1); out = h . cw2 + cb2
    {
        const float4* W4 = (const float4*)cw1;
        float4 acc = make_float4(0.f, 0.f, 0.f, 0.f);
        #pragma unroll
        for (int ii = 0; ii < 16; ii++) {
            float  s = sf[r * 16 + ii];
            float4 w = W4[(r * 16 + ii) * 64 + c];
            acc.x += s * w.x; acc.y += s * w.y; acc.z += s * w.z; acc.w += s * w.w;
        }
        part[r][c] = acc;
    }
    __syncthreads();
    #pragma unroll
    for (int s = 8; s > 0; s >>= 1) {
        if (r < s) {
            float4 o2 = part[r + s][c];
            part[r][c].x += o2.x; part[r][c].y += o2.y;
            part[r][c].z += o2.z; part[r][c].w += o2.w;
        }
        __syncthreads();
    }
    if (r == 0) {
        float4 cb = ((const float4*)cb1)[c];
        float4 w2 = ((const float4*)cw2)[c];
        float4 t = part[0][c];
        float h0 = fmaxf(t.x + cb.x, 0.f);
        float h1 = fmaxf(t.y + cb.y, 0.f);
        float h2 = fmaxf(t.z + cb.z, 0.f);
        float h3 = fmaxf(t.w + cb.w, 0.f);
        red[c] = h0 * w2.x + h1 * w2.y + h2 * w2.z + h3 * w2.w;
    }
    __syncthreads();
    if (tid < 32) {
        float s = red[tid] + red[tid + 32];
        #pragma unroll
        for (int o = 16; o > 0; o >>= 1) s += __shfl_xor_sync(0xffffffffu, s, o);
        if (tid == 0) out[b] = s + cb2[0];
    }
}

// ---------------- launch ----------------
extern "C" void kernel_launch(void* const* d_in, const int* in_sizes, int n_in,
                              void* d_out, int out_size) {
    const float* times   = (const float*)d_in[0];
    const int*   fid     = (const int*)  d_in[1];
    const float* values  = (const float*)d_in[2];
    const void*  mask    = (const void*) d_in[3];
    const float* me_w    = (const float*)d_in[4];
    const float* me_b    = (const float*)d_in[5];
    const float* var_emb = (const float*)d_in[6];
    const float* time_w  = (const float*)d_in[7];
    const float* time_b  = (const float*)d_in[8];
    const float* agg_w   = (const float*)d_in[9];
    const float* agg_b   = (const float*)d_in[10];
    const float* wq = (const float*)d_in[11]; const float* bq  = (const float*)d_in[12];
    const float* wk = (const float*)d_in[13]; const float* bk  = (const float*)d_in[14];
    const float* wv = (const float*)d_in[15]; const float* bvv = (const float*)d_in[16];
    const float* wo = (const float*)d_in[17]; const float* bo  = (const float*)d_in[18];
    const float* cw1 = (const float*)d_in[19]; const float* cb1 = (const float*)d_in[20];
    const float* cw2 = (const float*)d_in[21]; const float* cb2 = (const float*)d_in[22];
    float* out = (float*)d_out;

    k_init <<<ABC_BLKS + 8 + 8, 256>>>(me_w, me_b, time_w, time_b, agg_w, agg_b, mask);
    k_mid  <<<201 + NTOK / 256, 256>>>(var_emb, wq, bq, wk, bk, wv, bvv,
                                       fid, mask, values, times);
    k_attn <<<NBV, 256>>>(fid, values, times);
    k_final<<<8, 1024>>>(wo, bo, cw1, cb1, cw2, cb2, out);
}

// round 6
// speedup vs baseline: 3.0377x; 1.0743x over previous
#include <cuda_runtime.h>
#include <math.h>

#define Bc   8
#define Sc   8192
#define Vc   64
#define Dc   256
#define DVc  32
#define DAGG 224     // D - DV
#define NTOK (Bc*Sc) // 65536
#define NBV  (Bc*Vc) // 512
#define CAP  Sc      // worst-case tokens per (b,v) segment
#define ABC_BLKS 32

// ---------------- scratch (device globals; no allocation) ----------------
__device__ float  g_A[DAGG], g_Bv[DAGG], g_C[DAGG];
__device__ float  g_part[ABC_BLKS][3][DAGG];
__device__ int    g_abc_ctr = 0;                           // self-resetting
__device__ float  g_pa[3][Dc], g_pb[3][Dc], g_pc[3][Dc];   // 0=q,1=k,2=v
__device__ float  g_Pvar[3][Vc][Dc];                       // var_emb @ W[0:32,:]
__device__ int    g_cnt[NBV];
__device__ float2 g_tok[NBV * CAP];                        // (val,tt) per segment
__device__ float  g_ctx[Bc][Dc];
__device__ float  g_sf[Bc][Dc];
__device__ float  g_p2[Bc][8];
__device__ int    g_ctr2[Bc];                              // zero-init, self-resetting
__device__ int    g_maskflags = 0;   // bit0: byte layout, bit1: float layout (OR idempotent)

// ---------------- mask reader (dtype detected at runtime) ----------------
__device__ __forceinline__ bool is_valid(const void* mask, int t, int fl) {
    if (fl & 2) return ((const float*)mask)[t] != 0.0f;
    if (fl & 1) return ((const unsigned char*)mask)[t] != 0;
    return ((const int*)mask)[t] != 0;
}

// ---------------- K1: parallel ABC collapse + mask detect + zero ----------------
__global__ void k_init(const float* __restrict__ me_w, const float* __restrict__ me_b,
                       const float* __restrict__ time_w, const float* __restrict__ time_b,
                       const float* __restrict__ agg_w, const float* __restrict__ agg_b,
                       const void* __restrict__ mask) {
    int blk = blockIdx.x;
    if (blk < ABC_BLKS) {
        int j = threadIdx.x;
        __shared__ bool isLast;
        if (j < DAGG) {
            float a = 0.f, b = 0.f, c = 0.f;
            int i0 = blk * 16;
            #pragma unroll
            for (int ii = 0; ii < 16; ii++) {
                int i = i0 + ii;
                if (i < 256) {
                    float w = agg_w[i * DAGG + j];
                    a += me_w[i] * w;  c += me_b[i] * w;
                } else {
                    int k = i - 256;
                    float w = agg_w[(256 + k) * DAGG + j];
                    b += time_w[k] * w;  c += time_b[k] * w;
                }
            }
            g_part[blk][0][j] = a;
            g_part[blk][1][j] = b;
            g_part[blk][2][j] = c;
        }
        __threadfence();
        __syncthreads();
        if (threadIdx.x == 0)
            isLast = (atomicAdd(&g_abc_ctr, 1) == ABC_BLKS - 1);
        __syncthreads();
        if (isLast) {
            if (j < DAGG) {
                float a = 0.f, b = 0.f, c = 0.f;
                #pragma unroll
                for (int r = 0; r < ABC_BLKS; r++) {
                    a += g_part[r][0][j];
                    b += g_part[r][1][j];
                    c += g_part[r][2][j];
                }
                g_A[j] = a; g_Bv[j] = b; g_C[j] = c + agg_b[j];
            }
            if (threadIdx.x == 0) g_abc_ctr = 0;
        }
    } else if (blk < ABC_BLKS + 8) {
        const unsigned int* w32 = (const unsigned int*)mask;
        int flags = 0;
        int base = (blk - ABC_BLKS) * 2048 + threadIdx.x;
        #pragma unroll
        for (int t = 0; t < 8; t++) {
            unsigned int w = w32[base + t * 256];
            if (w == 0x3f800000u) flags |= 2;
            else if (w > 1u)      flags |= 1;
        }
        __shared__ int sfl;
        if (threadIdx.x == 0) sfl = 0;
        __syncthreads();
        if (flags) atomicOr(&sfl, flags);
        __syncthreads();
        if (threadIdx.x == 0 && sfl) atomicOr(&g_maskflags, sfl);
    } else {
        int i = (blk - ABC_BLKS - 8) * 256 + threadIdx.x;   // 0..2047
        if (i < NBV) g_cnt[i] = 0;
        ((float*)g_ctx)[i] = 0.f;
    }
}

// ---------------- K2: projection constants || vectorized token scatter ----------------
__global__ void k_mid(const float* __restrict__ var_emb,
                      const float* __restrict__ wq, const float* __restrict__ bq,
                      const float* __restrict__ wk, const float* __restrict__ bk,
                      const float* __restrict__ wv, const float* __restrict__ bvv,
                      const int* __restrict__ fid, const void* __restrict__ mask,
                      const float* __restrict__ values, const float* __restrict__ times) {
    int blk = blockIdx.x;
    if (blk < 201) {
        int p = blk / 67, row = blk % 67;
        const float* W  = (p == 0) ? wq : (p == 1 ? wk : wv);
        const float* bb = (p == 0) ? bq : (p == 1 ? bk : bvv);
        int j = threadIdx.x;
        if (row < Vc) {
            const float* ve = &var_emb[row * DVc];
            float s = 0.f;
            #pragma unroll
            for (int i = 0; i < DVc; i++) s += ve[i] * W[i * Dc + j];
            g_Pvar[p][row][j] = s;
        } else {
            const float* src = (row == Vc) ? g_A : (row == Vc + 1 ? g_Bv : g_C);
            float s = 0.f;
            #pragma unroll 8
            for (int i = 0; i < DAGG; i++) s += src[i] * W[(DVc + i) * Dc + j];
            if      (row == Vc)     g_pa[p][j] = s;
            else if (row == Vc + 1) g_pb[p][j] = s;
            else                    g_pc[p][j] = s + bb[j];
        }
    } else {
        // 4 tokens per thread, vectorized loads
        int t4 = (blk - 201) * 256 + threadIdx.x;   // token quad index
        int fl = g_maskflags;
        bool ok[4];
        if (fl & 2) {
            float4 m4 = ((const float4*)mask)[t4];
            ok[0] = m4.x != 0.f; ok[1] = m4.y != 0.f; ok[2] = m4.z != 0.f; ok[3] = m4.w != 0.f;
        } else if (fl & 1) {
            unsigned int u = ((const unsigned int*)mask)[t4];
            ok[0] = (u & 0xffu) != 0; ok[1] = (u & 0xff00u) != 0;
            ok[2] = (u & 0xff0000u) != 0; ok[3] = (u & 0xff000000u) != 0;
        } else {
            int4 m4 = ((const int4*)mask)[t4];
            ok[0] = m4.x != 0; ok[1] = m4.y != 0; ok[2] = m4.z != 0; ok[3] = m4.w != 0;
        }
        if (!(ok[0] | ok[1] | ok[2] | ok[3])) return;
        float4 vv = ((const float4*)values)[t4];
        float4 tt = ((const float4*)times)[t4];
        int4   ff = ((const int4*)fid)[t4];
        int b = (t4 * 4) >> 13;
        float va[4] = {vv.x, vv.y, vv.z, vv.w};
        float ta[4] = {tt.x, tt.y, tt.z, tt.w};
        int   fa[4] = {ff.x, ff.y, ff.z, ff.w};
        #pragma unroll
        for (int u = 0; u < 4; u++) {
            if (!ok[u]) continue;
            int bv = b * Vc + fa[u];
            int pos = atomicAdd(&g_cnt[bv], 1);
            g_tok[bv * CAP + pos] = make_float2(va[u], ta[u]);
        }
    }
}

// ---------------- K3: segmented attention, affine-score form ----------------
__global__ void __launch_bounds__(256) k_attn(const int* __restrict__ fid,
                                              const float* __restrict__ values,
                                              const float* __restrict__ times) {
    int bv = blockIdx.x;
    int b = bv >> 6, v = bv & (Vc - 1);
    int tid = threadIdx.x;             // dim index d = h*32+lane
    int lane = tid & 31;
    int n = g_cnt[bv];

    float va = g_pa[2][tid], vb = g_pb[2][tid], vc = g_pc[2][tid];

    if (n == 0) {
        int t0 = b * Sc;
        float vx = g_Pvar[2][fid[t0]][tid] + values[t0] * va + times[t0] * vb + vc;
        atomicAdd(&g_ctx[b][tid], vx);
        return;
    }

    const float2* tok = &g_tok[bv * CAP];

    float s_v = 0.f, s_t = 0.f;
    for (int i = lane; i < n; i += 32) {
        float2 vt = tok[i];
        s_v += vt.x; s_t += vt.y;
    }
    #pragma unroll
    for (int o = 16; o > 0; o >>= 1) {
        s_v += __shfl_xor_sync(0xffffffffu, s_v, o);
        s_t += __shfl_xor_sync(0xffffffffu, s_t, o);
    }
    float inv_n = 1.0f / (float)n;
    float mv = s_v * inv_n, mt = s_t * inv_n;

    float q  = g_Pvar[0][v][tid] + mv * g_pa[0][tid] + mt * g_pb[0][tid] + g_pc[0][tid];
    float kk = g_Pvar[1][v][tid] + g_pc[1][tid];

    const float scale = 0.17677669529663687f;  // 1/sqrt(32)
    float al = q * kk, be = q * g_pa[1][tid], ga = q * g_pb[1][tid];
    #pragma unroll
    for (int o = 16; o > 0; o >>= 1) {
        al += __shfl_xor_sync(0xffffffffu, al, o);
        be += __shfl_xor_sync(0xffffffffu, be, o);
        ga += __shfl_xor_sync(0xffffffffu, ga, o);
    }
    al *= scale; be *= scale; ga *= scale;

    float m = -1e30f, l = 0.f, sv = 0.f, st = 0.f;
    for (int i = lane; i < n; i += 32) {
        float2 vt = tok[i];
        float s  = al + be * vt.x + ga * vt.y;
        float nm = fmaxf(m, s);
        float c  = __expf(m - nm);
        float e  = __expf(s - nm);
        l  = l * c + e;
        sv = sv * c + e * vt.x;
        st = st * c + e * vt.y;
        m = nm;
    }
    #pragma unroll
    for (int o = 16; o > 0; o >>= 1) {
        float m2  = __shfl_xor_sync(0xffffffffu, m, o);
        float l2  = __shfl_xor_sync(0xffffffffu, l, o);
        float sv2 = __shfl_xor_sync(0xffffffffu, sv, o);
        float st2 = __shfl_xor_sync(0xffffffffu, st, o);
        float nm = fmaxf(m, m2);
        float c1 = __expf(m - nm), c2 = __expf(m2 - nm);
        l  = l * c1 + l2 * c2;
        sv = sv * c1 + sv2 * c2;
        st = st * c1 + st2 * c2;
        m = nm;
    }
    float wv = sv / l, wt = st / l;
    float ctx = g_Pvar[2][v][tid] + vc + wv * va + wt * vb;
    atomicAdd(&g_ctx[b][tid], ctx);
}

// ---------------- K4a: GEMV1 in 32-col slices (64 blocks) ----------------
__global__ void __launch_bounds__(256) k_f1(const float* __restrict__ wo,
                                            const float* __restrict__ bo) {
    int b = blockIdx.x >> 3, slice = blockIdx.x & 7;
    int tid = threadIdx.x;
    int col = tid & 31, r = tid >> 5;       // 8 row-partitions x 32 cols
    int jg = slice * 32 + col;              // global output column
    __shared__ float sm[Dc];
    __shared__ float part[8][32];

    sm[tid] = g_ctx[b][tid] * (1.0f / Vc);
    __syncthreads();

    float acc = 0.f;
    #pragma unroll
    for (int ii = 0; ii < 32; ii++) {
        int i = r * 32 + ii;
        acc += sm[i] * wo[i * Dc + jg];
    }
    part[r][col] = acc;
    __syncthreads();
    if (r < 4) part[r][col] += part[r + 4][col];
    __syncthreads();
    if (r == 0)
        g_sf[b][jg] = part[0][col] + part[1][col] + part[2][col] + part[3][col] + bo[jg];
}

// ---------------- K4b: GEMV2 + relu + dot, slice partials, last-block finalize ----------------
__global__ void __launch_bounds__(256) k_f2(const float* __restrict__ cw1,
                                            const float* __restrict__ cb1,
                                            const float* __restrict__ cw2,
                                            const float* __restrict__ cb2,
                                            float* __restrict__ out) {
    int b = blockIdx.x >> 3, slice = blockIdx.x & 7;
    int tid = threadIdx.x;
    int col = tid & 31, r = tid >> 5;
    int jg = slice * 32 + col;
    __shared__ float sf[Dc];
    __shared__ float part[8][32];

    sf[tid] = g_sf[b][tid];
    __syncthreads();

    float acc = 0.f;
    #pragma unroll
    for (int ii = 0; ii < 32; ii++) {
        int i = r * 32 + ii;
        acc += sf[i] * cw1[i * Dc + jg];
    }
    part[r][col] = acc;
    __syncthreads();
    if (r < 4) part[r][col] += part[r + 4][col];
    __syncthreads();
    if (r == 0) {
        float h = part[0][col] + part[1][col] + part[2][col] + part[3][col] + cb1[jg];
        h = fmaxf(h, 0.f);
        float s = h * cw2[jg];
        #pragma unroll
        for (int o = 16; o > 0; o >>= 1) s += __shfl_xor_sync(0xffffffffu, s, o);
        if (col == 0) {
            g_p2[b][slice] = s;
            __threadfence();
            int done = atomicAdd(&g_ctr2[b], 1);
            if (done == 7) {
                float tot = 0.f;
                #pragma unroll
                for (int k = 0; k < 8; k++) tot += g_p2[b][k];
                out[b] = tot + cb2[0];
                g_ctr2[b] = 0;   // reset for next replay
            }
        }
    }
}

// ---------------- launch ----------------
extern "C" void kernel_launch(void* const* d_in, const int* in_sizes, int n_in,
                              void* d_out, int out_size) {
    const float* times   = (const float*)d_in[0];
    const int*   fid     = (const int*)  d_in[1];
    const float* values  = (const float*)d_in[2];
    const void*  mask    = (const void*) d_in[3];
    const float* me_w    = (const float*)d_in[4];
    const float* me_b    = (const float*)d_in[5];
    const float* var_emb = (const float*)d_in[6];
    const float* time_w  = (const float*)d_in[7];
    const float* time_b  = (const float*)d_in[8];
    const float* agg_w   = (const float*)d_in[9];
    const float* agg_b   = (const float*)d_in[10];
    const float* wq = (const float*)d_in[11]; const float* bq  = (const float*)d_in[12];
    const float* wk = (const float*)d_in[13]; const float* bk  = (const float*)d_in[14];
    const float* wv = (const float*)d_in[15]; const float* bvv = (const float*)d_in[16];
    const float* wo = (const float*)d_in[17]; const float* bo  = (const float*)d_in[18];
    const float* cw1 = (const float*)d_in[19]; const float* cb1 = (const float*)d_in[20];
    const float* cw2 = (const float*)d_in[21]; const float* cb2 = (const float*)d_in[22];
    float* out = (float*)d_out;

    k_init <<<ABC_BLKS + 8 + 8, 256>>>(me_w, me_b, time_w, time_b, agg_w, agg_b, mask);
    k_mid  <<<201 + 64, 256>>>(var_emb, wq, bq, wk, bk, wv, bvv,
                               fid, mask, values, times);
    k_attn <<<NBV, 256>>>(fid, values, times);
    k_f1   <<<64, 256>>>(wo, bo);
    k_f2   <<<64, 256>>>(cw1, cb1, cw2, cb2, out);
}